// round 9
// baseline (speedup 1.0000x reference)
#include <cuda_runtime.h>
#include <cstdint>

// ===========================================================================
// FusionModel via mma.sync m16n8k16 fp16 — R4 GEMM verbatim; tail reworked.
//   H1pre = x @ W1,  x[b,(i*64+j)*64+k] = v1e[b,i]*v2e[b,j]*v3e[b,k]
//   M=256, N=256, K=262144. Grid: 2 mtiles x 74 K-chunks = 148 CTAs (1 wave).
// Per slab (R4-proven, untouched): B32 slab via cp.async double-buffered
//   swizzled; A rank-1 fp16 in smem from register v3; inline fp32->fp16 pack
//   at B-fragment load; 128 HMMA/warp/slab.
// Tail: coalesced float4 partial store (no atomics, no k_zero);
//   k_reduce sums the 74 chunks coalesced; k_epi finishes the MLP.
// ===========================================================================

namespace {
constexpr int BATCH = 256;
constexpr int DIN   = 63;
constexpr int H1    = 256;
constexpr int H2    = 128;
constexpr float EPSV  = 1e-5f;
constexpr float SLOPE = 0.1f;

constexpr int NSLABS  = 4096;
constexpr int NCHUNKS = 74;
constexpr int NT      = 256;

constexpr int SMB_BYTES = 65536;        // B slab: 64k x 256n fp32 (swizzled)
constexpr int SMA_BYTES = 128 * 144;    // A slab: 128 rows x (64 half + pad)
constexpr int SM_B   = 0;               // 2 x 64 KB
constexpr int SM_A   = 2 * SMB_BYTES;   // 131072, 2 x 18432
constexpr int SM_TOTAL = SM_A + 2 * SMA_BYTES;   // 167936 B
constexpr int A_WSTRIDE = 36;           // words per A row (144 B)
}

// per-(chunk,mtile) partial tiles [148][32768] + reduced H1pre [2][32768]
__device__ float g_part[2 * NCHUNKS * 32768];
__device__ float g_red[2 * 32768];

// ---- helpers --------------------------------------------------------------
__device__ __forceinline__ uint32_t smem_u32(const void* p) {
    uint32_t a;
    asm("{ .reg .u64 t; cvta.to.shared.u64 t, %1; cvt.u32.u64 %0, t; }"
        : "=r"(a) : "l"(p));
    return a;
}
__device__ __forceinline__ uint32_t pkh2(float lo, float hi) {
    uint32_t d;
    asm("cvt.rn.f16x2.f32 %0, %1, %2;" : "=r"(d) : "f"(hi), "f"(lo));
    return d;
}
__device__ __forceinline__ void mma_f16(float* c, const uint32_t* a,
                                        const uint32_t* b) {
    asm volatile(
        "mma.sync.aligned.m16n8k16.row.col.f32.f16.f16.f32 "
        "{%0,%1,%2,%3}, {%4,%5,%6,%7}, {%8,%9}, {%0,%1,%2,%3};"
        : "+f"(c[0]), "+f"(c[1]), "+f"(c[2]), "+f"(c[3])
        : "r"(a[0]), "r"(a[1]), "r"(a[2]), "r"(a[3]), "r"(b[0]), "r"(b[1]));
}
__device__ __forceinline__ void cp16(uint32_t dst, const void* src) {
    asm volatile("cp.async.cg.shared.global [%0], [%1], 16;"
                 :: "r"(dst), "l"(src));
}
#define CP_COMMIT() asm volatile("cp.async.commit_group;" ::: "memory")
#define CP_WAIT1()  asm volatile("cp.async.wait_group 1;" ::: "memory")
#define CP_WAIT0()  asm volatile("cp.async.wait_group 0;" ::: "memory")

// swizzled float index of B[k][n] (k:0..63, n:0..255), xor class (k>>1)&3
__device__ __forceinline__ int bidx(int k, int n) {
    return k * 256 + (((n >> 2) ^ (((k >> 1) & 3) << 1)) << 2) + (n & 3);
}

// ---------------------------------------------------------------------------
__global__ __launch_bounds__(NT, 1)
void k_gemm_mma(const float* __restrict__ v1, const float* __restrict__ v2,
                const float* __restrict__ v3, const float* __restrict__ W1) {
    extern __shared__ char smem[];
    float*    Bsm = (float*)(smem + SM_B);
    uint32_t* Asm = (uint32_t*)(smem + SM_A);   // [2][128 rows][36 words]
    const uint32_t b_u32 = smem_u32(Bsm);

    const int tid = threadIdx.x;
    const int wid = tid >> 5, l = tid & 31;
    const int lq = l >> 2, lr = l & 3;
    const int wm = wid >> 2, wn = wid & 3;
    const int mr = wm * 64, nc = wn * 64;

    const int mtile = blockIdx.x;
    const int chunk = blockIdx.y;
    const int s_lo = (chunk * NSLABS) / NCHUNKS;
    const int s_hi = ((chunk + 1) * NSLABS) / NCHUNKS;

    // A-gen ownership: row tb, k-half h; v3 register-resident
    const int tb = tid >> 1, h = tid & 1;
    const int bg = mtile * 128 + tb;
    float v3r[32];
#pragma unroll
    for (int q = 0; q < 32; ++q) {
        int kk = h * 32 + q;
        v3r[q] = (kk < DIN) ? v3[bg * DIN + kk] : 1.0f;
    }

    // cp ownership: row ck, n-window cq*64
    const int ck = tid & 63;
    const int cq = tid >> 6;

    auto issue = [&](int s, int p) {
        const float* base = W1 + (size_t)s * 64 * H1 + (size_t)ck * H1 + cq * 64;
        uint32_t bb = b_u32 + (uint32_t)p * SMB_BYTES;
#pragma unroll
        for (int it = 0; it < 16; ++it) {
            int ncx = cq * 16 + it;
            uint32_t dst = bb + (uint32_t)((ck * 64 + (ncx ^ (((ck >> 1) & 3) << 1))) * 16);
            cp16(dst, base + it * 4);
        }
        CP_COMMIT();
    };

    issue(s_lo, 0);
    if (s_lo + 1 < s_hi) issue(s_lo + 1, 1);

    float acc[4][8][4];
#pragma unroll
    for (int mt = 0; mt < 4; ++mt)
#pragma unroll
        for (int nt = 0; nt < 8; ++nt)
#pragma unroll
            for (int q = 0; q < 4; ++q) acc[mt][nt][q] = 0.0f;

    for (int s = s_lo; s < s_hi; ++s) {
        const int sl = s - s_lo;
        const int p = sl & 1;
        const float*    Bp = Bsm + p * (SMB_BYTES / 4);
        const uint32_t* Ap = Asm + p * (SMA_BYTES / 4);

        // ---- A gen: fp16 A[row][k] = cvt(s(b) * v3[b,k]) ----
        {
            int i = s >> 6, j = s & 63;
            float ai = (i < DIN) ? __ldg(v1 + bg * DIN + i) : 1.0f;
            float cj = (j < DIN) ? __ldg(v2 + bg * DIN + j) : 1.0f;
            float sv = ai * cj;
            uint32_t* dst = (uint32_t*)(smem + SM_A + p * SMA_BYTES) +
                            tb * A_WSTRIDE + h * 16;
#pragma unroll
            for (int g = 0; g < 4; ++g) {
                uint4 v;
                v.x = pkh2(sv * v3r[g * 8 + 0], sv * v3r[g * 8 + 1]);
                v.y = pkh2(sv * v3r[g * 8 + 2], sv * v3r[g * 8 + 3]);
                v.z = pkh2(sv * v3r[g * 8 + 4], sv * v3r[g * 8 + 5]);
                v.w = pkh2(sv * v3r[g * 8 + 6], sv * v3r[g * 8 + 7]);
                *(uint4*)(dst + g * 4) = v;
            }
        }

        if (s + 1 < s_hi) { CP_WAIT1(); } else { CP_WAIT0(); }
        __syncthreads();

#pragma unroll
        for (int kk = 0; kk < 4; ++kk) {
            const int kw = kk * 8 + lr;     // word offset within A row
            const int kb = kk * 16;         // k base for B
            uint32_t a[4][4];
#pragma unroll
            for (int mt = 0; mt < 4; ++mt) {
                const uint32_t* ar = Ap + (mr + mt * 16 + lq) * A_WSTRIDE;
                a[mt][0] = ar[kw];
                a[mt][1] = ar[8 * A_WSTRIDE + kw];
                a[mt][2] = ar[kw + 4];
                a[mt][3] = ar[8 * A_WSTRIDE + kw + 4];
            }
            const int k0 = kb + lr * 2;
            uint32_t bfr[8][2];
#pragma unroll
            for (int nt = 0; nt < 8; ++nt) {
                const int n = nc + nt * 8 + lq;
                bfr[nt][0] = pkh2(Bp[bidx(k0, n)],     Bp[bidx(k0 + 1, n)]);
                bfr[nt][1] = pkh2(Bp[bidx(k0 + 8, n)], Bp[bidx(k0 + 9, n)]);
            }
#pragma unroll
            for (int mt = 0; mt < 4; ++mt)
#pragma unroll
                for (int nt = 0; nt < 8; ++nt)
                    mma_f16(acc[mt][nt], a[mt], bfr[nt]);
        }
        __syncthreads();

        if (s + 2 < s_hi) issue(s + 2, p);
    }

    // ---- coalesced partial store: g_part[chunk*2+mtile][wid][mt*8+nt][l*4+q]
    float* part = g_part + ((size_t)(chunk * 2 + mtile)) * 32768 + wid * 4096;
#pragma unroll
    for (int mt = 0; mt < 4; ++mt)
#pragma unroll
        for (int nt = 0; nt < 8; ++nt)
            *(float4*)(part + (mt * 8 + nt) * 128 + l * 4) =
                make_float4(acc[mt][nt][0], acc[mt][nt][1],
                            acc[mt][nt][2], acc[mt][nt][3]);
}

// ---------------------------------------------------------------------------
// reduce 74 chunks: g_red[mtile][off] = sum_c g_part[c*2+mtile][off]
__global__ __launch_bounds__(1024)
void k_reduce() {
    const int idx = blockIdx.x * 1024 + threadIdx.x;   // 0..65535
    const int mtile = idx >> 15;
    const int off = idx & 32767;
    const float* src = g_part + (size_t)mtile * 32768 + off;
    float x = 0.0f;
#pragma unroll 8
    for (int c = 0; c < NCHUNKS; ++c) x += src[(size_t)c * 65536];
    g_red[idx] = x;
}

// ---------------------------------------------------------------------------
__global__ __launch_bounds__(H1)
void k_epi(const float* __restrict__ b1,  const float* __restrict__ g1,
           const float* __restrict__ be1, const float* __restrict__ rm1,
           const float* __restrict__ rv1, const float* __restrict__ W2,
           const float* __restrict__ b2,  const float* __restrict__ g2,
           const float* __restrict__ be2, const float* __restrict__ rm2,
           const float* __restrict__ rv2, const float* __restrict__ Wc,
           const float* __restrict__ bc,  float* __restrict__ out) {
    __shared__ float h1s[H1];
    __shared__ float red[H2];
    const int b = blockIdx.x;
    const int t = threadIdx.x;      // h index, 256 threads

    // locate (b, h=t) inside the warp-partial layout (validated in R8)
    const int mtile = b >> 7, rr = b & 127;
    const int wm = rr >> 6, mt = (rr >> 4) & 3, ph = (rr >> 3) & 1, plq = rr & 7;
    const int wn = t >> 6, nt = (t >> 3) & 7, plr = (t & 7) >> 1, cpar = t & 1;
    const int wid = wm * 4 + wn, q = ph * 2 + cpar;

    float x = g_red[mtile * 32768 + wid * 4096 +
                    (mt * 8 + nt) * 128 + (plq * 4 + plr) * 4 + q];

    x += b1[t];
    x = (x >= 0.0f) ? x : SLOPE * x;
    x = (x - rm1[t]) * rsqrtf(rv1[t] + EPSV) * g1[t] + be1[t];
    h1s[t] = x;
    __syncthreads();

    if (t < H2) {
        float a = 0.0f;
#pragma unroll 8
        for (int i = 0; i < H1; i++) a += h1s[i] * W2[i * H2 + t];
        a += b2[t];
        a = (a >= 0.0f) ? a : SLOPE * a;
        a = (a - rm2[t]) * rsqrtf(rv2[t] + EPSV) * g2[t] + be2[t];
        red[t] = a * Wc[t];
    }
    for (int sft = H2 / 2; sft > 0; sft >>= 1) {
        __syncthreads();
        if (t < sft) red[t] += red[t + sft];
    }
    __syncthreads();
    if (t == 0) out[b] = red[0] + bc[0];
}

// ---------------------------------------------------------------------------
extern "C" void kernel_launch(void* const* d_in, const int* in_sizes, int n_in,
                              void* d_out, int out_size) {
    const float* vec1  = (const float*)d_in[0];
    const float* vec2  = (const float*)d_in[1];
    const float* vec3  = (const float*)d_in[2];
    const float* W1    = (const float*)d_in[3];
    const float* b1    = (const float*)d_in[4];
    const float* g1    = (const float*)d_in[5];
    const float* beta1 = (const float*)d_in[6];
    const float* rm1   = (const float*)d_in[7];
    const float* rv1   = (const float*)d_in[8];
    const float* W2    = (const float*)d_in[9];
    const float* b2    = (const float*)d_in[10];
    const float* g2    = (const float*)d_in[11];
    const float* beta2 = (const float*)d_in[12];
    const float* rm2   = (const float*)d_in[13];
    const float* rv2   = (const float*)d_in[14];
    const float* Wc    = (const float*)d_in[15];
    const float* bc    = (const float*)d_in[16];
    float* out = (float*)d_out;

    cudaFuncSetAttribute(k_gemm_mma,
                         cudaFuncAttributeMaxDynamicSharedMemorySize, SM_TOTAL);

    dim3 grid(2, NCHUNKS);   // 148 CTAs = 1 wave
    k_gemm_mma<<<grid, NT, SM_TOTAL>>>(vec1, vec2, vec3, W1);

    k_reduce<<<64, 1024>>>();

    k_epi<<<BATCH, H1>>>(b1, g1, beta1, rm1, rv1, W2, b2, g2, beta2,
                         rm2, rv2, Wc, bc, out);
}

// round 10
// speedup vs baseline: 1.0257x; 1.0257x over previous
#include <cuda_runtime.h>
#include <cstdint>

// ===========================================================================
// FusionModel via mma.sync m16n8k16 fp16 — R4 structure, 512-thread re-tile.
//   H1pre = x @ W1,  x[b,(i*64+j)*64+k] = v1e[b,i]*v2e[b,j]*v3e[b,k]
//   M=256, N=256, K=262144. Grid: 2 mtiles x 74 K-chunks = 148 CTAs (1 wave).
// 16 warps/CTA (4 per SMSP) in a 2x8 grid: warp tile 64 rows x 32 cols,
//   acc[4][4][4]=64 regs -> ~125 regs/thread, no spills, 2x latency hiding.
// Per slab (R4-proven): B32 slab via cp.async double-buffered swizzled;
//   A rank-1 fp16 in smem from register v3 (16/thread); inline fp32->fp16
//   pack at B-fragment load; 64 HMMA/warp/slab. atomicAdd split-K tail.
// Last slab peeled so its cp.async gets a full wait_group 0.
// ===========================================================================

namespace {
constexpr int BATCH = 256;
constexpr int DIN   = 63;
constexpr int H1    = 256;
constexpr int H2    = 128;
constexpr float EPSV  = 1e-5f;
constexpr float SLOPE = 0.1f;

constexpr int NSLABS  = 4096;
constexpr int NCHUNKS = 74;
constexpr int NT      = 512;

constexpr int SMB_BYTES = 65536;        // B slab: 64k x 256n fp32 (swizzled)
constexpr int SMA_BYTES = 128 * 144;    // A slab: 128 rows x (64 half + pad)
constexpr int SM_B   = 0;               // 2 x 64 KB
constexpr int SM_A   = 2 * SMB_BYTES;   // 131072, 2 x 18432
constexpr int SM_TOTAL = SM_A + 2 * SMA_BYTES;   // 167936 B
constexpr int A_WSTRIDE = 36;           // words per A row (144 B)
}

__device__ float g_acc[BATCH * H1];

__global__ void k_zero() {
    int i = blockIdx.x * blockDim.x + threadIdx.x;
    if (i < BATCH * H1) g_acc[i] = 0.0f;
}

// ---- helpers --------------------------------------------------------------
__device__ __forceinline__ uint32_t smem_u32(const void* p) {
    uint32_t a;
    asm("{ .reg .u64 t; cvta.to.shared.u64 t, %1; cvt.u32.u64 %0, t; }"
        : "=r"(a) : "l"(p));
    return a;
}
__device__ __forceinline__ uint32_t pkh2(float lo, float hi) {
    uint32_t d;
    asm("cvt.rn.f16x2.f32 %0, %1, %2;" : "=r"(d) : "f"(hi), "f"(lo));
    return d;
}
__device__ __forceinline__ void mma_f16(float* c, const uint32_t* a,
                                        const uint32_t* b) {
    asm volatile(
        "mma.sync.aligned.m16n8k16.row.col.f32.f16.f16.f32 "
        "{%0,%1,%2,%3}, {%4,%5,%6,%7}, {%8,%9}, {%0,%1,%2,%3};"
        : "+f"(c[0]), "+f"(c[1]), "+f"(c[2]), "+f"(c[3])
        : "r"(a[0]), "r"(a[1]), "r"(a[2]), "r"(a[3]), "r"(b[0]), "r"(b[1]));
}
__device__ __forceinline__ void cp16(uint32_t dst, const void* src) {
    asm volatile("cp.async.cg.shared.global [%0], [%1], 16;"
                 :: "r"(dst), "l"(src));
}
#define CP_COMMIT() asm volatile("cp.async.commit_group;" ::: "memory")
#define CP_WAIT1()  asm volatile("cp.async.wait_group 1;" ::: "memory")
#define CP_WAIT0()  asm volatile("cp.async.wait_group 0;" ::: "memory")

// swizzled float index of B[k][n] (k:0..63, n:0..255), xor class (k>>1)&3
__device__ __forceinline__ int bidx(int k, int n) {
    return k * 256 + (((n >> 2) ^ (((k >> 1) & 3) << 1)) << 2) + (n & 3);
}

// ---------------------------------------------------------------------------
__global__ __launch_bounds__(NT, 1)
void k_gemm_mma(const float* __restrict__ v1, const float* __restrict__ v2,
                const float* __restrict__ v3, const float* __restrict__ W1) {
    extern __shared__ char smem[];
    float*    Bsm = (float*)(smem + SM_B);
    uint32_t* Asm = (uint32_t*)(smem + SM_A);   // [2][128 rows][36 words]
    const uint32_t b_u32 = smem_u32(Bsm);

    const int tid = threadIdx.x;
    const int wid = tid >> 5, l = tid & 31;
    const int lq = l >> 2, lr = l & 3;
    const int wm = wid >> 3, wn = wid & 7;       // 2 x 8 warp grid
    const int mr = wm * 64, nc = wn * 32;

    const int mtile = blockIdx.x;
    const int chunk = blockIdx.y;
    const int s_lo = (chunk * NSLABS) / NCHUNKS;
    const int s_hi = ((chunk + 1) * NSLABS) / NCHUNKS;

    // A-gen ownership: row tb (0..127), k-quarter qq; v3 register-resident
    const int tb = tid >> 2, qq = tid & 3;
    const int bg = mtile * 128 + tb;
    float v3r[16];
#pragma unroll
    for (int q = 0; q < 16; ++q) {
        int kk = qq * 16 + q;
        v3r[q] = (kk < DIN) ? v3[bg * DIN + kk] : 1.0f;
    }

    // cp ownership: row ck (0..63), n-window cq*32 (cq 0..7)
    const int ck = tid & 63;
    const int cq = tid >> 6;

    auto issue = [&](int s, int p) {
        const float* base = W1 + (size_t)s * 64 * H1 + (size_t)ck * H1 + cq * 32;
        uint32_t bb = b_u32 + (uint32_t)p * SMB_BYTES;
#pragma unroll
        for (int it = 0; it < 8; ++it) {
            int ncx = cq * 8 + it;
            uint32_t dst = bb + (uint32_t)((ck * 64 + (ncx ^ (((ck >> 1) & 3) << 1))) * 16);
            cp16(dst, base + it * 4);
        }
        CP_COMMIT();
    };

    issue(s_lo, 0);
    if (s_lo + 1 < s_hi) issue(s_lo + 1, 1);

    float acc[4][4][4];
#pragma unroll
    for (int mt = 0; mt < 4; ++mt)
#pragma unroll
        for (int nt = 0; nt < 4; ++nt)
#pragma unroll
            for (int q = 0; q < 4; ++q) acc[mt][nt][q] = 0.0f;

    // ---- per-slab phases (shared by main loop and peeled last slab) ----
    auto agen = [&](int s, int p) {
        int i = s >> 6, j = s & 63;
        float ai = (i < DIN) ? __ldg(v1 + bg * DIN + i) : 1.0f;
        float cj = (j < DIN) ? __ldg(v2 + bg * DIN + j) : 1.0f;
        float sv = ai * cj;
        uint32_t* dst = (uint32_t*)(smem + SM_A + p * SMA_BYTES) +
                        tb * A_WSTRIDE + qq * 8;
#pragma unroll
        for (int g = 0; g < 2; ++g) {
            uint4 v;
            v.x = pkh2(sv * v3r[g * 8 + 0], sv * v3r[g * 8 + 1]);
            v.y = pkh2(sv * v3r[g * 8 + 2], sv * v3r[g * 8 + 3]);
            v.z = pkh2(sv * v3r[g * 8 + 4], sv * v3r[g * 8 + 5]);
            v.w = pkh2(sv * v3r[g * 8 + 6], sv * v3r[g * 8 + 7]);
            *(uint4*)(dst + g * 4) = v;
        }
    };

    auto mma_slab = [&](int p) {
        const float*    Bp = Bsm + p * (SMB_BYTES / 4);
        const uint32_t* Ap = Asm + p * (SMA_BYTES / 4);
#pragma unroll
        for (int kk = 0; kk < 4; ++kk) {
            const int kw = kk * 8 + lr;
            uint32_t a[4][4];
#pragma unroll
            for (int mt = 0; mt < 4; ++mt) {
                const uint32_t* ar = Ap + (mr + mt * 16 + lq) * A_WSTRIDE;
                a[mt][0] = ar[kw];
                a[mt][1] = ar[8 * A_WSTRIDE + kw];
                a[mt][2] = ar[kw + 4];
                a[mt][3] = ar[8 * A_WSTRIDE + kw + 4];
            }
            const int k0 = kk * 16 + lr * 2;
            uint32_t bfr[4][2];
#pragma unroll
            for (int nt = 0; nt < 4; ++nt) {
                const int n = nc + nt * 8 + lq;
                bfr[nt][0] = pkh2(Bp[bidx(k0, n)],     Bp[bidx(k0 + 1, n)]);
                bfr[nt][1] = pkh2(Bp[bidx(k0 + 8, n)], Bp[bidx(k0 + 9, n)]);
            }
#pragma unroll
            for (int mt = 0; mt < 4; ++mt)
#pragma unroll
                for (int nt = 0; nt < 4; ++nt)
                    mma_f16(acc[mt][nt], a[mt], bfr[nt]);
        }
    };

    // main loop (all but last slab) — branch-free body, R4 schedule
    for (int s = s_lo; s < s_hi - 1; ++s) {
        const int p = (s - s_lo) & 1;
        agen(s, p);
        CP_WAIT1();
        __syncthreads();
        mma_slab(p);
        __syncthreads();
        if (s + 2 < s_hi) issue(s + 2, p);
    }
    // peeled last slab — full wait so its cp.async data is guaranteed
    {
        const int p = (s_hi - 1 - s_lo) & 1;
        agen(s_hi - 1, p);
        CP_WAIT0();
        __syncthreads();
        mma_slab(p);
    }

    // ---- split-K reduction (R4-proven atomic tail) ----
#pragma unroll
    for (int mt = 0; mt < 4; ++mt) {
        const int row = mtile * 128 + mr + mt * 16 + lq;
#pragma unroll
        for (int nt = 0; nt < 4; ++nt) {
            const int col = nc + nt * 8 + lr * 2;
            atomicAdd(g_acc + row * H1 + col,           acc[mt][nt][0]);
            atomicAdd(g_acc + row * H1 + col + 1,       acc[mt][nt][1]);
            atomicAdd(g_acc + (row + 8) * H1 + col,     acc[mt][nt][2]);
            atomicAdd(g_acc + (row + 8) * H1 + col + 1, acc[mt][nt][3]);
        }
    }
}

// ---------------------------------------------------------------------------
__global__ __launch_bounds__(H2)
void k_epi(const float* __restrict__ b1,  const float* __restrict__ g1,
           const float* __restrict__ be1, const float* __restrict__ rm1,
           const float* __restrict__ rv1, const float* __restrict__ W2,
           const float* __restrict__ b2,  const float* __restrict__ g2,
           const float* __restrict__ be2, const float* __restrict__ rm2,
           const float* __restrict__ rv2, const float* __restrict__ Wc,
           const float* __restrict__ bc,  float* __restrict__ out) {
    __shared__ float h1s[H1];
    __shared__ float red[H2];
    const int b = blockIdx.x;
    const int t = threadIdx.x;

    for (int h = t; h < H1; h += H2) {
        float x = g_acc[b * H1 + h] + b1[h];
        x = (x >= 0.0f) ? x : SLOPE * x;
        x = (x - rm1[h]) * rsqrtf(rv1[h] + EPSV) * g1[h] + be1[h];
        h1s[h] = x;
    }
    __syncthreads();

    float a = 0.0f;
#pragma unroll 8
    for (int i = 0; i < H1; i++) a += h1s[i] * W2[i * H2 + t];
    a += b2[t];
    a = (a >= 0.0f) ? a : SLOPE * a;
    a = (a - rm2[t]) * rsqrtf(rv2[t] + EPSV) * g2[t] + be2[t];
    red[t] = a * Wc[t];
    __syncthreads();

    for (int sft = H2 / 2; sft > 0; sft >>= 1) {
        if (t < sft) red[t] += red[t + sft];
        __syncthreads();
    }
    if (t == 0) out[b] = red[0] + bc[0];
}

// ---------------------------------------------------------------------------
extern "C" void kernel_launch(void* const* d_in, const int* in_sizes, int n_in,
                              void* d_out, int out_size) {
    const float* vec1  = (const float*)d_in[0];
    const float* vec2  = (const float*)d_in[1];
    const float* vec3  = (const float*)d_in[2];
    const float* W1    = (const float*)d_in[3];
    const float* b1    = (const float*)d_in[4];
    const float* g1    = (const float*)d_in[5];
    const float* beta1 = (const float*)d_in[6];
    const float* rm1   = (const float*)d_in[7];
    const float* rv1   = (const float*)d_in[8];
    const float* W2    = (const float*)d_in[9];
    const float* b2    = (const float*)d_in[10];
    const float* g2    = (const float*)d_in[11];
    const float* beta2 = (const float*)d_in[12];
    const float* rm2   = (const float*)d_in[13];
    const float* rv2   = (const float*)d_in[14];
    const float* Wc    = (const float*)d_in[15];
    const float* bc    = (const float*)d_in[16];
    float* out = (float*)d_out;

    cudaFuncSetAttribute(k_gemm_mma,
                         cudaFuncAttributeMaxDynamicSharedMemorySize, SM_TOTAL);

    k_zero<<<(BATCH * H1 + 1023) / 1024, 1024>>>();

    dim3 grid(2, NCHUNKS);   // 148 CTAs = 1 wave
    k_gemm_mma<<<grid, NT, SM_TOTAL>>>(vec1, vec2, vec3, W1);

    k_epi<<<BATCH, H2>>>(b1, g1, beta1, rm1, rv1, W2, b2, g2, beta2,
                         rm2, rv2, Wc, bc, out);
}